// round 8
// baseline (speedup 1.0000x reference)
#include <cuda_runtime.h>

#define TB 32      // threads per block (main kernel) = 1 warp
#define EPT 4      // batch elements per thread (2 f32x2 packs)
#define MAXB 131072

typedef unsigned long long u64;

// scratch: z transposed [48][B], en staged [48][B]
__device__ float g_zt[(size_t)48 * MAXB];
__device__ float g_en[(size_t)48 * MAXB];

__device__ __forceinline__ u64 pk(float lo, float hi) {
    u64 r; asm("mov.b64 %0,{%1,%2};" : "=l"(r) : "f"(lo), "f"(hi)); return r;
}
__device__ __forceinline__ void upk(u64 v, float& lo, float& hi) {
    asm("mov.b64 {%0,%1},%2;" : "=f"(lo), "=f"(hi) : "l"(v));
}
__device__ __forceinline__ u64 ffma2(u64 a, u64 b, u64 c) {
    u64 d; asm("fma.rn.f32x2 %0,%1,%2,%3;" : "=l"(d) : "l"(a), "l"(b), "l"(c)); return d;
}
__device__ __forceinline__ float tanha(float x) {
    float y; asm("tanh.approx.f32 %0,%1;" : "=f"(y) : "f"(x)); return y;
}
__device__ __forceinline__ float sigm(float x) {
    return fmaf(tanha(0.5f * x), 0.5f, 0.5f);
}

struct __align__(16) SW {
    u64 Wih2[256];    // main LSTM input weights, dup pairs [64 rows][4]
    u64 Whh2[1024];   // main LSTM hidden weights, dup pairs [64 rows][16]
    u64 Weih2[256];   // encoder LSTM input weights
    u64 Wehh2[1024];  // encoder LSTM hidden weights
    u64 Bm2[64];      // (b_ih+b_hh) dup
    u64 Be2[64];      // (be_ih+be_hh) dup
    float Wlf[12 * 16];  // linear layer weights, padded rows (13 used of 16)
    float Blf[12];
    float W1[128];
    float W2[32];
    float Wenc[64];
    float B1[8];
    float B2m[4];
    float Benc[4];
    float gg[8];      // Wg[0..2], bg, Wg2[0..2], bg2
    float lut[128 * 4];  // final per-element projections for cooperative write
};

// One LSTM step for 4 batch elements (2 f32x2 packs). Weight loads amortized
// 4 ways; cell state c lives in SMEM (cs, stride TB) to stay under the RF cap.
__device__ __forceinline__ void cell4p(
    const u64* __restrict__ wi,    // [64][4] dup pairs
    const u64* __restrict__ wh,    // [64][16] dup pairs
    const u64* __restrict__ bias,  // [64] dup pairs
    const u64 (&za)[4][2], u64 (&h)[16][2], ulonglong2* __restrict__ cs)
{
    const ulonglong2* wi2 = (const ulonglong2*)wi;
    const ulonglong2* wh2 = (const ulonglong2*)wh;
    u64 hn[16][2];
#pragma unroll 4
    for (int u = 0; u < 16; u++) {
        ulonglong2 cc = cs[u * TB];   // independent of MAC chains -> scheduled early
        u64 A[4][2];
#pragma unroll
        for (int g = 0; g < 4; g++) { u64 b = bias[u + 16 * g]; A[g][0] = b; A[g][1] = b; }
#pragma unroll
        for (int m = 0; m < 2; m++) {
#pragma unroll
            for (int g = 0; g < 4; g++) {
                ulonglong2 w = wi2[(u + 16 * g) * 2 + m];
#pragma unroll
                for (int p = 0; p < 2; p++) {
                    A[g][p] = ffma2(za[2 * m][p], w.x, A[g][p]);
                    A[g][p] = ffma2(za[2 * m + 1][p], w.y, A[g][p]);
                }
            }
        }
#pragma unroll
        for (int m = 0; m < 8; m++) {
#pragma unroll
            for (int g = 0; g < 4; g++) {
                ulonglong2 w = wh2[(u + 16 * g) * 8 + m];
#pragma unroll
                for (int p = 0; p < 2; p++) {
                    A[g][p] = ffma2(h[2 * m][p], w.x, A[g][p]);
                    A[g][p] = ffma2(h[2 * m + 1][p], w.y, A[g][p]);
                }
            }
        }
        u64 nc[2];
#pragma unroll
        for (int p = 0; p < 2; p++) {
            float i0, i1, f0, f1, g0, g1, o0, o1, cl, ch;
            upk(A[0][p], i0, i1); upk(A[1][p], f0, f1);
            upk(A[2][p], g0, g1); upk(A[3][p], o0, o1);
            upk(p ? cc.y : cc.x, cl, ch);
            cl = sigm(f0) * cl + sigm(i0) * tanha(g0);
            ch = sigm(f1) * ch + sigm(i1) * tanha(g1);
            nc[p] = pk(cl, ch);
            hn[u][p] = pk(sigm(o0) * tanha(cl), sigm(o1) * tanha(ch));
        }
        cs[u * TB] = make_ulonglong2(nc[0], nc[1]);
    }
#pragma unroll
    for (int k = 0; k < 16; k++) { h[k][0] = hn[k][0]; h[k][1] = hn[k][1]; }
}

// Transpose z [B][48] -> g_zt [48][B] so the main kernel's recurrent loads coalesce.
__global__ void zt_kernel(const float* __restrict__ z, int B)
{
    __shared__ float ts[64 * 49];
    const int e0 = blockIdx.x * 64;
    const int cnt = min(64, B - e0);
    const float4* zp = (const float4*)(z + (size_t)e0 * 48);
    for (int i = threadIdx.x; i < 768; i += 256) {
        int base = i * 4;
        int el = base / 48, v = base % 48;
        if (el < cnt) {
            float4 w = zp[i];
            ts[el * 49 + v] = w.x; ts[el * 49 + v + 1] = w.y;
            ts[el * 49 + v + 2] = w.z; ts[el * 49 + v + 3] = w.w;
        }
    }
    __syncthreads();
    for (int i = threadIdx.x; i < 3072; i += 256) {
        int v = i >> 6, el = i & 63;
        if (el < cnt)
            g_zt[(size_t)v * B + e0 + el] = ts[el * 49 + v];
    }
}

__global__ void __launch_bounds__(TB, 6) stae_main(
    const float* __restrict__ x,
    const float* __restrict__ W_ih, const float* __restrict__ W_hh,
    const float* __restrict__ b_ih, const float* __restrict__ b_hh,
    const float* __restrict__ mW1, const float* __restrict__ mb1,
    const float* __restrict__ mW2, const float* __restrict__ mb2,
    const float* __restrict__ Wg, const float* __restrict__ bg,
    const float* __restrict__ Wg2, const float* __restrict__ bg2,
    const float* __restrict__ Wl, const float* __restrict__ bl,
    const float* __restrict__ We_ih, const float* __restrict__ We_hh,
    const float* __restrict__ be_ih, const float* __restrict__ be_hh,
    const float* __restrict__ Wenc, const float* __restrict__ benc,
    float* __restrict__ out, int B)
{
    __shared__ SW s;
    __shared__ ulonglong2 c_sh[16 * TB];   // cell state: [unit][tid], 16B each
    const int tid = threadIdx.x;

    for (int i = tid; i < 256; i += TB) {
        s.Wih2[i] = pk(W_ih[i], W_ih[i]);
        s.Weih2[i] = pk(We_ih[i], We_ih[i]);
    }
    for (int i = tid; i < 1024; i += TB) {
        s.Whh2[i] = pk(W_hh[i], W_hh[i]);
        s.Wehh2[i] = pk(We_hh[i], We_hh[i]);
    }
    for (int i = tid; i < 64; i += TB) {
        s.Bm2[i] = pk(b_ih[i] + b_hh[i], b_ih[i] + b_hh[i]);
        s.Be2[i] = pk(be_ih[i] + be_hh[i], be_ih[i] + be_hh[i]);
        s.Wenc[i] = Wenc[i];
    }
    for (int i = tid; i < 156; i += TB) s.Wlf[(i / 13) * 16 + (i % 13)] = Wl[i];
    for (int i = tid; i < 128; i += TB) s.W1[i] = mW1[i];
    if (tid < 32) s.W2[tid] = mW2[tid];
    if (tid < 12) s.Blf[tid] = bl[tid];
    if (tid < 8)  s.B1[tid] = mb1[tid];
    if (tid < 4)  { s.B2m[tid] = mb2[tid]; s.Benc[tid] = benc[tid]; }
    if (tid < 3)  { s.gg[tid] = Wg[tid]; s.gg[4 + tid] = Wg2[tid]; }
    if (tid == 3) { s.gg[3] = bg[0]; s.gg[7] = bg2[0]; }
    __syncthreads();

    const int warpBase = blockIdx.x * (TB * EPT);   // 128 elements per warp
    const int e0 = warpBase + tid * EPT;            // 4 consecutive elements
    const int e0c = (e0 + EPT <= B) ? e0 : (B > EPT ? B - EPT : 0);  // clamped for vector loads

    ulonglong2* cs = c_sh + tid;   // stride TB between units
    u64 h[16][2];
    u64 za[4][2];
#pragma unroll
    for (int k = 0; k < 16; k++) { h[k][0] = h[k][1] = 0ull; cs[k * TB] = make_ulonglong2(0ull, 0ull); }

    // ---------------- phase 1: main LSTM over z_t (coalesced) ----------------
    {
        float4 zv[4], zn[4];
#pragma unroll
        for (int q = 0; q < 4; q++) zv[q] = *(const float4*)(g_zt + (size_t)q * B + e0c);
#pragma unroll 1
        for (int t = 0; t < 12; t++) {
            if (t < 11) {
#pragma unroll
                for (int q = 0; q < 4; q++)
                    zn[q] = *(const float4*)(g_zt + (size_t)((t + 1) * 4 + q) * B + e0c);
            }
#pragma unroll
            for (int q = 0; q < 4; q++) {
                za[q][0] = pk(zv[q].x, zv[q].y);
                za[q][1] = pk(zv[q].z, zv[q].w);
            }
            cell4p(s.Wih2, s.Whh2, s.Bm2, za, h, cs);
#pragma unroll
            for (int q = 0; q < 4; q++) zv[q] = zn[q];
        }
    }

    // ------------- epilogue: per-element mlp -> gcn2 -> v_out -> en ----------
#pragma unroll 1
    for (int j = 0; j < EPT; j++) {
        const int p = j >> 1, hi = j & 1;
        float hs[16];
#pragma unroll
        for (int k = 0; k < 16; k++) {
            float a, b; upk(h[k][p], a, b); hs[k] = hi ? b : a;
        }
        float m1[8];
#pragma unroll
        for (int jj = 0; jj < 8; jj++) {
            float a = s.B1[jj];
#pragma unroll
            for (int k = 0; k < 16; k++) a += hs[k] * s.W1[jj * 16 + k];
            m1[jj] = fmaxf(a, 0.f);
        }
        float mo[4];
#pragma unroll
        for (int n = 0; n < 4; n++) {
            float a = s.B2m[n];
#pragma unroll
            for (int jj = 0; jj < 8; jj++) a += m1[jj] * s.W2[n * 8 + jj];
            mo[n] = a;
        }
        // GCN2 on mlp output (path graph 0-1-2-3)
        float q0 = s.gg[4], q1 = s.gg[5], q2 = s.gg[6], qb = s.gg[7];
        float x1_0 = mo[1], x1_1 = mo[0] + mo[2], x1_2 = mo[1] + mo[3], x1_3 = mo[2];
        float x2_0 = x1_1, x2_1 = x1_0 + x1_2, x2_2 = x1_1 + x1_3, x2_3 = x1_2;
        float mg[4];
        mg[0] = q0 * mo[0] + q1 * x1_0 + q2 * x2_0 + qb;
        mg[1] = q0 * mo[1] + q1 * x1_1 + q2 * x2_1 + qb;
        mg[2] = q0 * mo[2] + q1 * x1_2 + q2 * x2_2 + qb;
        mg[3] = q0 * mo[3] + q1 * x1_3 + q2 * x2_3 + qb;

        const int e = e0c + j;
        float xr[48];
        {
            const float4* xb = (const float4*)(x + (size_t)e * 48);
#pragma unroll
            for (int q = 0; q < 12; q++) {
                float4 v = xb[q];
                xr[q * 4 + 0] = v.x; xr[q * 4 + 1] = v.y;
                xr[q * 4 + 2] = v.z; xr[q * 4 + 3] = v.w;
            }
        }
        const float g0_ = s.gg[0], g1_ = s.gg[1], g2_ = s.gg[2], gb_ = s.gg[3];
        const bool wr = (e0 + j) < B;
#pragma unroll 1
        for (int t = 0; t < 12; t++) {
            float vc[4];
#pragma unroll
            for (int n = 0; n < 4; n++) {
                float a = s.Blf[t] + mg[n] * s.Wlf[t * 16 + 12];
#pragma unroll
                for (int k = 0; k < 12; k++) a += xr[n * 12 + k] * s.Wlf[t * 16 + k];
                vc[n] = a;
            }
            float xc0 = xr[t], xc1 = xr[12 + t], xc2 = xr[24 + t], xc3 = xr[36 + t];
            float a1_0 = xc1, a1_1 = xc0 + xc2, a1_2 = xc1 + xc3, a1_3 = xc2;
            float a2_0 = a1_1, a2_1 = a1_0 + a1_2, a2_2 = a1_1 + a1_3, a2_3 = a1_2;
            float d1_0 = vc[1], d1_1 = vc[0] + vc[2], d1_2 = vc[1] + vc[3], d1_3 = vc[2];
            float d2_0 = d1_1, d2_1 = d1_0 + d1_2, d2_2 = d1_1 + d1_3, d2_3 = d1_2;
            float en0 = g0_ * xc0 + g1_ * a1_0 + g2_ * a2_0 + gb_ + q0 * vc[0] + q1 * d1_0 + q2 * d2_0 + qb;
            float en1 = g0_ * xc1 + g1_ * a1_1 + g2_ * a2_1 + gb_ + q0 * vc[1] + q1 * d1_1 + q2 * d2_1 + qb;
            float en2 = g0_ * xc2 + g1_ * a1_2 + g2_ * a2_2 + gb_ + q0 * vc[2] + q1 * d1_2 + q2 * d2_2 + qb;
            float en3 = g0_ * xc3 + g1_ * a1_3 + g2_ * a2_3 + gb_ + q0 * vc[3] + q1 * d1_3 + q2 * d2_3 + qb;
            if (wr) {
                g_en[(size_t)(0 * 12 + t) * B + e] = en0;
                g_en[(size_t)(1 * 12 + t) * B + e] = en1;
                g_en[(size_t)(2 * 12 + t) * B + e] = en2;
                g_en[(size_t)(3 * 12 + t) * B + e] = en3;
            }
        }
    }

    // ---------------- phase 3: encoder LSTM over en (coalesced) ---------------
#pragma unroll
    for (int k = 0; k < 16; k++) { h[k][0] = h[k][1] = 0ull; cs[k * TB] = make_ulonglong2(0ull, 0ull); }
    {
        float4 ev[4], en2[4];
#pragma unroll
        for (int n = 0; n < 4; n++) ev[n] = *(const float4*)(g_en + (size_t)(n * 12) * B + e0c);
#pragma unroll 1
        for (int t = 0; t < 12; t++) {
            if (t < 11) {
#pragma unroll
                for (int n = 0; n < 4; n++)
                    en2[n] = *(const float4*)(g_en + (size_t)(n * 12 + t + 1) * B + e0c);
            }
#pragma unroll
            for (int n = 0; n < 4; n++) {
                za[n][0] = pk(ev[n].x, ev[n].y);
                za[n][1] = pk(ev[n].z, ev[n].w);
            }
            cell4p(s.Weih2, s.Wehh2, s.Be2, za, h, cs);
#pragma unroll
            for (int n = 0; n < 4; n++) ev[n] = en2[n];
        }
    }

    // ---------------- final projection -> SMEM lut -> cooperative write -------
#pragma unroll 1
    for (int j = 0; j < EPT; j++) {
        const int p = j >> 1, hi = j & 1;
        float hs[16];
#pragma unroll
        for (int k = 0; k < 16; k++) {
            float a, b; upk(h[k][p], a, b); hs[k] = hi ? b : a;
        }
#pragma unroll
        for (int n = 0; n < 4; n++) {
            float a = s.Benc[n];
#pragma unroll
            for (int k = 0; k < 16; k++) a += hs[k] * s.Wenc[n * 16 + k];
            s.lut[(tid * EPT + j) * 4 + n] = a;
        }
    }
    __syncwarp();

    // warp block = 128 rows x 48 floats = 1536 float4s, coalesced
    float4* ob = (float4*)(out + (size_t)warpBase * 48);
#pragma unroll 1
    for (int r = 0; r < 48; r++) {
        int f = r * TB + tid;
        int el = f / 12;          // local element 0..127
        int jj = f % 12;          // float4 index within row
        if (warpBase + el < B) {
            float v = s.lut[el * 4 + jj / 3];
            ob[f] = make_float4(v, v, v, v);
        }
    }
}

extern "C" void kernel_launch(void* const* d_in, const int* in_sizes, int n_in,
                              void* d_out, int out_size)
{
    const float* x     = (const float*)d_in[0];
    const float* z     = (const float*)d_in[1];
    const float* W_ih  = (const float*)d_in[2];
    const float* W_hh  = (const float*)d_in[3];
    const float* b_ih  = (const float*)d_in[4];
    const float* b_hh  = (const float*)d_in[5];
    const float* mW1   = (const float*)d_in[6];
    const float* mb1   = (const float*)d_in[7];
    const float* mW2   = (const float*)d_in[8];
    const float* mb2   = (const float*)d_in[9];
    const float* Wg    = (const float*)d_in[10];
    const float* bg    = (const float*)d_in[11];
    const float* Wg2   = (const float*)d_in[12];
    const float* bg2   = (const float*)d_in[13];
    const float* Wl    = (const float*)d_in[14];
    const float* bl    = (const float*)d_in[15];
    const float* We_ih = (const float*)d_in[16];
    const float* We_hh = (const float*)d_in[17];
    const float* be_ih = (const float*)d_in[18];
    const float* be_hh = (const float*)d_in[19];
    const float* Wenc  = (const float*)d_in[20];
    const float* benc  = (const float*)d_in[21];

    int B = in_sizes[0] / 48;   // x is [B, 12, 4]
    zt_kernel<<<(B + 63) / 64, 256>>>(z, B);
    stae_main<<<(B + TB * EPT - 1) / (TB * EPT), TB>>>(
        x, W_ih, W_hh, b_ih, b_hh, mW1, mb1, mW2, mb2,
        Wg, bg, Wg2, bg2, Wl, bl, We_ih, We_hh, be_ih, be_hh,
        Wenc, benc, (float*)d_out, B);
}

// round 10
// speedup vs baseline: 1.2659x; 1.2659x over previous
#include <cuda_runtime.h>

#define TB 64      // threads per block = 2 warps (weights SMEM amortized)
#define EPT 4      // batch elements per thread (2 f32x2 packs)
#define ELPB (TB * EPT)   // 256 elements per CTA
#define MAXB 131072

typedef unsigned long long u64;

// scratch: z transposed [48][B], en staged [48][B]
__device__ float g_zt[(size_t)48 * MAXB];
__device__ float g_en[(size_t)48 * MAXB];

__device__ __forceinline__ u64 pk(float lo, float hi) {
    u64 r; asm("mov.b64 %0,{%1,%2};" : "=l"(r) : "f"(lo), "f"(hi)); return r;
}
__device__ __forceinline__ void upk(u64 v, float& lo, float& hi) {
    asm("mov.b64 {%0,%1},%2;" : "=f"(lo), "=f"(hi) : "l"(v));
}
__device__ __forceinline__ u64 ffma2(u64 a, u64 b, u64 c) {
    u64 d; asm("fma.rn.f32x2 %0,%1,%2,%3;" : "=l"(d) : "l"(a), "l"(b), "l"(c)); return d;
}
__device__ __forceinline__ float tanha(float x) {
    float y; asm("tanh.approx.f32 %0,%1;" : "=f"(y) : "f"(x)); return y;
}
__device__ __forceinline__ float sigm(float x) {
    return fmaf(tanha(0.5f * x), 0.5f, 0.5f);
}

struct __align__(16) SW {
    u64 Wih2[256];    // main LSTM input weights, dup pairs [64 rows][4]
    u64 Whh2[1024];   // main LSTM hidden weights, dup pairs [64 rows][16]
    u64 Weih2[256];   // encoder LSTM input weights
    u64 Wehh2[1024];  // encoder LSTM hidden weights
    u64 Bm2[64];      // (b_ih+b_hh) dup
    u64 Be2[64];      // (be_ih+be_hh) dup
    float Wlf[12 * 16];  // linear layer weights, padded rows (13 used of 16)
    float Blf[12];
    float W1[128];
    float W2[32];
    float Wenc[64];
    float B1[8];
    float B2m[4];
    float Benc[4];
    float gg[8];      // Wg[0..2], bg, Wg2[0..2], bg2
    float lut[ELPB * 4];  // final per-element projections for cooperative write
};

// One LSTM step for 4 batch elements (2 f32x2 packs). Weight loads amortized
// 4 ways; cell state c lives in SMEM (cs, stride TB) to stay under the RF cap.
__device__ __forceinline__ void cell4p(
    const u64* __restrict__ wi,    // [64][4] dup pairs
    const u64* __restrict__ wh,    // [64][16] dup pairs
    const u64* __restrict__ bias,  // [64] dup pairs
    const u64 (&za)[4][2], u64 (&h)[16][2], ulonglong2* __restrict__ cs)
{
    const ulonglong2* wi2 = (const ulonglong2*)wi;
    const ulonglong2* wh2 = (const ulonglong2*)wh;
    u64 hn[16][2];
#pragma unroll 4
    for (int u = 0; u < 16; u++) {
        ulonglong2 cc = cs[u * TB];   // independent of MAC chains -> scheduled early
        u64 A[4][2];
#pragma unroll
        for (int g = 0; g < 4; g++) { u64 b = bias[u + 16 * g]; A[g][0] = b; A[g][1] = b; }
#pragma unroll
        for (int m = 0; m < 2; m++) {
#pragma unroll
            for (int g = 0; g < 4; g++) {
                ulonglong2 w = wi2[(u + 16 * g) * 2 + m];
#pragma unroll
                for (int p = 0; p < 2; p++) {
                    A[g][p] = ffma2(za[2 * m][p], w.x, A[g][p]);
                    A[g][p] = ffma2(za[2 * m + 1][p], w.y, A[g][p]);
                }
            }
        }
#pragma unroll
        for (int m = 0; m < 8; m++) {
#pragma unroll
            for (int g = 0; g < 4; g++) {
                ulonglong2 w = wh2[(u + 16 * g) * 8 + m];
#pragma unroll
                for (int p = 0; p < 2; p++) {
                    A[g][p] = ffma2(h[2 * m][p], w.x, A[g][p]);
                    A[g][p] = ffma2(h[2 * m + 1][p], w.y, A[g][p]);
                }
            }
        }
        u64 nc[2];
#pragma unroll
        for (int p = 0; p < 2; p++) {
            float i0, i1, f0, f1, g0, g1, o0, o1, cl, ch;
            upk(A[0][p], i0, i1); upk(A[1][p], f0, f1);
            upk(A[2][p], g0, g1); upk(A[3][p], o0, o1);
            upk(p ? cc.y : cc.x, cl, ch);
            cl = sigm(f0) * cl + sigm(i0) * tanha(g0);
            ch = sigm(f1) * ch + sigm(i1) * tanha(g1);
            nc[p] = pk(cl, ch);
            hn[u][p] = pk(sigm(o0) * tanha(cl), sigm(o1) * tanha(ch));
        }
        cs[u * TB] = make_ulonglong2(nc[0], nc[1]);
    }
#pragma unroll
    for (int k = 0; k < 16; k++) { h[k][0] = hn[k][0]; h[k][1] = hn[k][1]; }
}

// Transpose z [B][48] -> g_zt [48][B] so the main kernel's recurrent loads coalesce.
__global__ void zt_kernel(const float* __restrict__ z, int B)
{
    __shared__ float ts[64 * 49];
    const int e0 = blockIdx.x * 64;
    const int cnt = min(64, B - e0);
    const float4* zp = (const float4*)(z + (size_t)e0 * 48);
    for (int i = threadIdx.x; i < 768; i += 256) {
        int base = i * 4;
        int el = base / 48, v = base % 48;
        if (el < cnt) {
            float4 w = zp[i];
            ts[el * 49 + v] = w.x; ts[el * 49 + v + 1] = w.y;
            ts[el * 49 + v + 2] = w.z; ts[el * 49 + v + 3] = w.w;
        }
    }
    __syncthreads();
    for (int i = threadIdx.x; i < 3072; i += 256) {
        int v = i >> 6, el = i & 63;
        if (el < cnt)
            g_zt[(size_t)v * B + e0 + el] = ts[el * 49 + v];
    }
}

__global__ void __launch_bounds__(TB, 4) stae_main(
    const float* __restrict__ x,
    const float* __restrict__ W_ih, const float* __restrict__ W_hh,
    const float* __restrict__ b_ih, const float* __restrict__ b_hh,
    const float* __restrict__ mW1, const float* __restrict__ mb1,
    const float* __restrict__ mW2, const float* __restrict__ mb2,
    const float* __restrict__ Wg, const float* __restrict__ bg,
    const float* __restrict__ Wg2, const float* __restrict__ bg2,
    const float* __restrict__ Wl, const float* __restrict__ bl,
    const float* __restrict__ We_ih, const float* __restrict__ We_hh,
    const float* __restrict__ be_ih, const float* __restrict__ be_hh,
    const float* __restrict__ Wenc, const float* __restrict__ benc,
    float* __restrict__ out, int B)
{
    __shared__ SW s;
    __shared__ ulonglong2 c_sh[16 * TB];   // cell state: [unit][tid], 16B each
    const int tid = threadIdx.x;
    const int lane = tid & 31;
    const int warp = tid >> 5;

    for (int i = tid; i < 256; i += TB) {
        s.Wih2[i] = pk(W_ih[i], W_ih[i]);
        s.Weih2[i] = pk(We_ih[i], We_ih[i]);
    }
    for (int i = tid; i < 1024; i += TB) {
        s.Whh2[i] = pk(W_hh[i], W_hh[i]);
        s.Wehh2[i] = pk(We_hh[i], We_hh[i]);
    }
    for (int i = tid; i < 64; i += TB) {
        s.Bm2[i] = pk(b_ih[i] + b_hh[i], b_ih[i] + b_hh[i]);
        s.Be2[i] = pk(be_ih[i] + be_hh[i], be_ih[i] + be_hh[i]);
        s.Wenc[i] = Wenc[i];
    }
    for (int i = tid; i < 156; i += TB) s.Wlf[(i / 13) * 16 + (i % 13)] = Wl[i];
    for (int i = tid; i < 128; i += TB) s.W1[i] = mW1[i];
    if (tid < 32) s.W2[tid] = mW2[tid];
    if (tid < 12) s.Blf[tid] = bl[tid];
    if (tid < 8)  s.B1[tid] = mb1[tid];
    if (tid < 4)  { s.B2m[tid] = mb2[tid]; s.Benc[tid] = benc[tid]; }
    if (tid < 3)  { s.gg[tid] = Wg[tid]; s.gg[4 + tid] = Wg2[tid]; }
    if (tid == 3) { s.gg[3] = bg[0]; s.gg[7] = bg2[0]; }
    __syncthreads();

    const int warpBase = blockIdx.x * ELPB + warp * 128;  // 128 elements per warp
    const int e0 = warpBase + lane * EPT;                 // 4 consecutive elements
    const int e0c = (e0 + EPT <= B) ? e0 : (B > EPT ? B - EPT : 0);  // clamped for vector loads

    ulonglong2* cs = c_sh + tid;   // stride TB between units
    u64 h[16][2];
    u64 za[4][2];
#pragma unroll
    for (int k = 0; k < 16; k++) { h[k][0] = h[k][1] = 0ull; cs[k * TB] = make_ulonglong2(0ull, 0ull); }

    // ---------------- phase 1: main LSTM over z_t (coalesced) ----------------
    {
        float4 zv[4], zn[4];
#pragma unroll
        for (int q = 0; q < 4; q++) zv[q] = *(const float4*)(g_zt + (size_t)q * B + e0c);
#pragma unroll 1
        for (int t = 0; t < 12; t++) {
            if (t < 11) {
#pragma unroll
                for (int q = 0; q < 4; q++)
                    zn[q] = *(const float4*)(g_zt + (size_t)((t + 1) * 4 + q) * B + e0c);
            }
#pragma unroll
            for (int q = 0; q < 4; q++) {
                za[q][0] = pk(zv[q].x, zv[q].y);
                za[q][1] = pk(zv[q].z, zv[q].w);
            }
            cell4p(s.Wih2, s.Whh2, s.Bm2, za, h, cs);
#pragma unroll
            for (int q = 0; q < 4; q++) zv[q] = zn[q];
        }
    }

    // ------------- epilogue: per-element mlp -> gcn2 -> v_out -> en ----------
#pragma unroll 1
    for (int j = 0; j < EPT; j++) {
        const int p = j >> 1, hi = j & 1;
        float hs[16];
#pragma unroll
        for (int k = 0; k < 16; k++) {
            float a, b; upk(h[k][p], a, b); hs[k] = hi ? b : a;
        }
        float m1[8];
#pragma unroll
        for (int jj = 0; jj < 8; jj++) {
            float a = s.B1[jj];
#pragma unroll
            for (int k = 0; k < 16; k++) a += hs[k] * s.W1[jj * 16 + k];
            m1[jj] = fmaxf(a, 0.f);
        }
        float mo[4];
#pragma unroll
        for (int n = 0; n < 4; n++) {
            float a = s.B2m[n];
#pragma unroll
            for (int jj = 0; jj < 8; jj++) a += m1[jj] * s.W2[n * 8 + jj];
            mo[n] = a;
        }
        // GCN2 on mlp output (path graph 0-1-2-3)
        float q0 = s.gg[4], q1 = s.gg[5], q2 = s.gg[6], qb = s.gg[7];
        float x1_0 = mo[1], x1_1 = mo[0] + mo[2], x1_2 = mo[1] + mo[3], x1_3 = mo[2];
        float x2_0 = x1_1, x2_1 = x1_0 + x1_2, x2_2 = x1_1 + x1_3, x2_3 = x1_2;
        float mg[4];
        mg[0] = q0 * mo[0] + q1 * x1_0 + q2 * x2_0 + qb;
        mg[1] = q0 * mo[1] + q1 * x1_1 + q2 * x2_1 + qb;
        mg[2] = q0 * mo[2] + q1 * x1_2 + q2 * x2_2 + qb;
        mg[3] = q0 * mo[3] + q1 * x1_3 + q2 * x2_3 + qb;

        const int e = e0c + j;
        float xr[48];
        {
            const float4* xb = (const float4*)(x + (size_t)e * 48);
#pragma unroll
            for (int q = 0; q < 12; q++) {
                float4 v = xb[q];
                xr[q * 4 + 0] = v.x; xr[q * 4 + 1] = v.y;
                xr[q * 4 + 2] = v.z; xr[q * 4 + 3] = v.w;
            }
        }
        const float g0_ = s.gg[0], g1_ = s.gg[1], g2_ = s.gg[2], gb_ = s.gg[3];
        const bool wr = (e0 + j) < B;
#pragma unroll 1
        for (int t = 0; t < 12; t++) {
            float vc[4];
#pragma unroll
            for (int n = 0; n < 4; n++) {
                float a = s.Blf[t] + mg[n] * s.Wlf[t * 16 + 12];
#pragma unroll
                for (int k = 0; k < 12; k++) a += xr[n * 12 + k] * s.Wlf[t * 16 + k];
                vc[n] = a;
            }
            float xc0 = xr[t], xc1 = xr[12 + t], xc2 = xr[24 + t], xc3 = xr[36 + t];
            float a1_0 = xc1, a1_1 = xc0 + xc2, a1_2 = xc1 + xc3, a1_3 = xc2;
            float a2_0 = a1_1, a2_1 = a1_0 + a1_2, a2_2 = a1_1 + a1_3, a2_3 = a1_2;
            float d1_0 = vc[1], d1_1 = vc[0] + vc[2], d1_2 = vc[1] + vc[3], d1_3 = vc[2];
            float d2_0 = d1_1, d2_1 = d1_0 + d1_2, d2_2 = d1_1 + d1_3, d2_3 = d1_2;
            float en0 = g0_ * xc0 + g1_ * a1_0 + g2_ * a2_0 + gb_ + q0 * vc[0] + q1 * d1_0 + q2 * d2_0 + qb;
            float en1 = g0_ * xc1 + g1_ * a1_1 + g2_ * a2_1 + gb_ + q0 * vc[1] + q1 * d1_1 + q2 * d2_1 + qb;
            float en2 = g0_ * xc2 + g1_ * a1_2 + g2_ * a2_2 + gb_ + q0 * vc[2] + q1 * d1_2 + q2 * d2_2 + qb;
            float en3 = g0_ * xc3 + g1_ * a1_3 + g2_ * a2_3 + gb_ + q0 * vc[3] + q1 * d1_3 + q2 * d2_3 + qb;
            if (wr) {
                g_en[(size_t)(0 * 12 + t) * B + e] = en0;
                g_en[(size_t)(1 * 12 + t) * B + e] = en1;
                g_en[(size_t)(2 * 12 + t) * B + e] = en2;
                g_en[(size_t)(3 * 12 + t) * B + e] = en3;
            }
        }
    }

    // ---------------- phase 3: encoder LSTM over en (coalesced) ---------------
#pragma unroll
    for (int k = 0; k < 16; k++) { h[k][0] = h[k][1] = 0ull; cs[k * TB] = make_ulonglong2(0ull, 0ull); }
    {
        float4 ev[4], en2[4];
#pragma unroll
        for (int n = 0; n < 4; n++) ev[n] = *(const float4*)(g_en + (size_t)(n * 12) * B + e0c);
#pragma unroll 1
        for (int t = 0; t < 12; t++) {
            if (t < 11) {
#pragma unroll
                for (int n = 0; n < 4; n++)
                    en2[n] = *(const float4*)(g_en + (size_t)(n * 12 + t + 1) * B + e0c);
            }
#pragma unroll
            for (int n = 0; n < 4; n++) {
                za[n][0] = pk(ev[n].x, ev[n].y);
                za[n][1] = pk(ev[n].z, ev[n].w);
            }
            cell4p(s.Weih2, s.Wehh2, s.Be2, za, h, cs);
#pragma unroll
            for (int n = 0; n < 4; n++) ev[n] = en2[n];
        }
    }

    // ---------------- final projection -> SMEM lut -> cooperative write -------
#pragma unroll 1
    for (int j = 0; j < EPT; j++) {
        const int p = j >> 1, hi = j & 1;
        float hs[16];
#pragma unroll
        for (int k = 0; k < 16; k++) {
            float a, b; upk(h[k][p], a, b); hs[k] = hi ? b : a;
        }
#pragma unroll
        for (int n = 0; n < 4; n++) {
            float a = s.Benc[n];
#pragma unroll
            for (int k = 0; k < 16; k++) a += hs[k] * s.Wenc[n * 16 + k];
            s.lut[(tid * EPT + j) * 4 + n] = a;
        }
    }
    __syncwarp();

    // per-warp block = 128 rows x 48 floats = 1536 float4s, coalesced
    float4* ob = (float4*)(out + (size_t)warpBase * 48);
#pragma unroll 1
    for (int r = 0; r < 48; r++) {
        int f = r * 32 + lane;
        int el = f / 12;          // local element 0..127 within warp's block
        int jj = f % 12;          // float4 index within row
        if (warpBase + el < B) {
            float v = s.lut[(warp * 128 + el) * 4 + jj / 3];
            ob[f] = make_float4(v, v, v, v);
        }
    }
}

extern "C" void kernel_launch(void* const* d_in, const int* in_sizes, int n_in,
                              void* d_out, int out_size)
{
    const float* x     = (const float*)d_in[0];
    const float* z     = (const float*)d_in[1];
    const float* W_ih  = (const float*)d_in[2];
    const float* W_hh  = (const float*)d_in[3];
    const float* b_ih  = (const float*)d_in[4];
    const float* b_hh  = (const float*)d_in[5];
    const float* mW1   = (const float*)d_in[6];
    const float* mb1   = (const float*)d_in[7];
    const float* mW2   = (const float*)d_in[8];
    const float* mb2   = (const float*)d_in[9];
    const float* Wg    = (const float*)d_in[10];
    const float* bg    = (const float*)d_in[11];
    const float* Wg2   = (const float*)d_in[12];
    const float* bg2   = (const float*)d_in[13];
    const float* Wl    = (const float*)d_in[14];
    const float* bl    = (const float*)d_in[15];
    const float* We_ih = (const float*)d_in[16];
    const float* We_hh = (const float*)d_in[17];
    const float* be_ih = (const float*)d_in[18];
    const float* be_hh = (const float*)d_in[19];
    const float* Wenc  = (const float*)d_in[20];
    const float* benc  = (const float*)d_in[21];

    int B = in_sizes[0] / 48;   // x is [B, 12, 4]
    zt_kernel<<<(B + 63) / 64, 256>>>(z, B);
    stae_main<<<(B + ELPB - 1) / ELPB, TB>>>(
        x, W_ih, W_hh, b_ih, b_hh, mW1, mb1, mW2, mb2,
        Wg, bg, Wg2, bg2, Wl, bl, We_ih, We_hh, be_ih, be_hh,
        Wenc, benc, (float*)d_out, B);
}

// round 11
// speedup vs baseline: 1.3909x; 1.0987x over previous
#include <cuda_runtime.h>

#define TB 64      // threads per block = 2 warps
#define EPT 4      // batch elements per thread
#define ELPB (TB * EPT)   // 256 elements per CTA
#define MAXB 131072

typedef unsigned long long u64;

// scratch: z transposed [48][B], en staged [48][B]
__device__ float g_zt[(size_t)48 * MAXB];
__device__ float g_en[(size_t)48 * MAXB];

__device__ __forceinline__ u64 pk(float lo, float hi) {
    u64 r; asm("mov.b64 %0,{%1,%2};" : "=l"(r) : "f"(lo), "f"(hi)); return r;
}
__device__ __forceinline__ void upk(u64 v, float& lo, float& hi) {
    asm("mov.b64 {%0,%1},%2;" : "=f"(lo), "=f"(hi) : "l"(v));
}
__device__ __forceinline__ u64 ffma2(u64 a, u64 b, u64 c) {
    u64 d; asm("fma.rn.f32x2 %0,%1,%2,%3;" : "=l"(d) : "l"(a), "l"(b), "l"(c)); return d;
}
__device__ __forceinline__ float tanha(float x) {
    float y; asm("tanh.approx.f32 %0,%1;" : "=f"(y) : "f"(x)); return y;
}
// gate pre-activations for i/f/o are PRE-SCALED by 0.5 in the weights,
// so sigmoid(x) = 0.5 + 0.5*tanh(x/2) becomes one fmaf on the raw gate value.
__device__ __forceinline__ float sigp(float a_half) {
    return fmaf(tanha(a_half), 0.5f, 0.5f);
}

#define COMP(v, e) ((e) == 0 ? (v).x : (e) == 1 ? (v).y : (e) == 2 ? (v).z : (v).w)

struct __align__(16) SW {
    u64 Wim[128];   // main LSTM input pairs  [64 rows][2]  (real pairs, scaled)
    u64 Whm[512];   // main LSTM hidden pairs [64 rows][8]
    u64 Wie[128];   // encoder input pairs
    u64 Whe[512];   // encoder hidden pairs
    u64 Bm[64];     // (scaled bias, 0)
    u64 Be[64];
    float Wlf[12 * 16];  // linear layer, padded rows
    float Blf[12];
    float W1[128];
    float W2[32];
    float Wenc[64];
    float B1[8];
    float B2m[4];
    float Benc[4];
    float gg[8];    // Wg[0..2], bg, Wg2[0..2], bg2
};

// One LSTM step, 4 elements/thread, unit-packed f32x2:
//   hp[e][m] = (h[2m], h[2m+1]) of element e  -- real weight pairs, no dup.
// New h streams to SMEM (hw) during the unit loop; hp reloaded at cell end.
// Cell state c lives in SMEM as float4 (4 elements).
__device__ __forceinline__ void cell4u(
    const u64* __restrict__ wi,    // [64][2] pairs
    const u64* __restrict__ wh,    // [64][8] pairs
    const u64* __restrict__ bias,  // [64] (b,0)
    const u64 (&xe)[4][2], u64 (&hp)[4][8],
    float4* __restrict__ cs, float* __restrict__ hw, int tid)
{
    const ulonglong2* wi2 = (const ulonglong2*)wi;   // 1 load = row's 2 pairs
    const ulonglong2* wh2 = (const ulonglong2*)wh;   // [row][4], 2 pairs each
#pragma unroll 4
    for (int u = 0; u < 16; u++) {
        float4 cc = cs[u * TB];
        u64 A[4][4];   // [gate][elem], lo=even-k partial (+bias), hi=odd-k partial
#pragma unroll
        for (int g = 0; g < 4; g++) {
            u64 b = bias[u + 16 * g];
#pragma unroll
            for (int e = 0; e < 4; e++) A[g][e] = b;
        }
#pragma unroll
        for (int g = 0; g < 4; g++) {
            ulonglong2 w = wi2[u + 16 * g];
#pragma unroll
            for (int e = 0; e < 4; e++) {
                A[g][e] = ffma2(xe[e][0], w.x, A[g][e]);
                A[g][e] = ffma2(xe[e][1], w.y, A[g][e]);
            }
        }
#pragma unroll
        for (int m = 0; m < 4; m++) {
#pragma unroll
            for (int g = 0; g < 4; g++) {
                ulonglong2 w = wh2[(u + 16 * g) * 4 + m];
#pragma unroll
                for (int e = 0; e < 4; e++) {
                    A[g][e] = ffma2(hp[e][2 * m], w.x, A[g][e]);
                    A[g][e] = ffma2(hp[e][2 * m + 1], w.y, A[g][e]);
                }
            }
        }
        float cn4[4];
#pragma unroll
        for (int e = 0; e < 4; e++) {
            float il, ih, fl, fh, gl, gh, ol, oh;
            upk(A[0][e], il, ih); upk(A[1][e], fl, fh);
            upk(A[2][e], gl, gh); upk(A[3][e], ol, oh);
            float iv = il + ih, fv = fl + fh, gv = gl + gh, ov = ol + oh;
            float ci = sigp(iv);
            float cf = sigp(fv);
            float os = sigp(ov);
            float gt = tanha(gv);   // g gate stored unscaled
            float cold = COMP(cc, e);
            float cn = cf * cold + ci * gt;
            cn4[e] = cn;
            float hv = os * tanha(cn);
            hw[(((e * 8 + (u >> 1)) * TB) + tid) * 2 + (u & 1)] = hv;
        }
        cs[u * TB] = make_float4(cn4[0], cn4[1], cn4[2], cn4[3]);
    }
    // reload h pairs for the next step (same-thread SMEM RAW: ordered)
#pragma unroll
    for (int e = 0; e < 4; e++)
#pragma unroll
        for (int m = 0; m < 8; m++)
            hp[e][m] = *(const u64*)&hw[((e * 8 + m) * TB + tid) * 2];
}

// Transpose z [B][48] -> g_zt [48][B] for coalesced recurrent loads.
__global__ void zt_kernel(const float* __restrict__ z, int B)
{
    __shared__ float ts[64 * 49];
    const int e0 = blockIdx.x * 64;
    const int cnt = min(64, B - e0);
    const float4* zp = (const float4*)(z + (size_t)e0 * 48);
    for (int i = threadIdx.x; i < 768; i += 256) {
        int base = i * 4;
        int el = base / 48, v = base % 48;
        if (el < cnt) {
            float4 w = zp[i];
            ts[el * 49 + v] = w.x; ts[el * 49 + v + 1] = w.y;
            ts[el * 49 + v + 2] = w.z; ts[el * 49 + v + 3] = w.w;
        }
    }
    __syncthreads();
    for (int i = threadIdx.x; i < 3072; i += 256) {
        int v = i >> 6, el = i & 63;
        if (el < cnt)
            g_zt[(size_t)v * B + e0 + el] = ts[el * 49 + v];
    }
}

__global__ void __launch_bounds__(TB, 4) stae_main(
    const float* __restrict__ x,
    const float* __restrict__ W_ih, const float* __restrict__ W_hh,
    const float* __restrict__ b_ih, const float* __restrict__ b_hh,
    const float* __restrict__ mW1, const float* __restrict__ mb1,
    const float* __restrict__ mW2, const float* __restrict__ mb2,
    const float* __restrict__ Wg, const float* __restrict__ bg,
    const float* __restrict__ Wg2, const float* __restrict__ bg2,
    const float* __restrict__ Wl, const float* __restrict__ bl,
    const float* __restrict__ We_ih, const float* __restrict__ We_hh,
    const float* __restrict__ be_ih, const float* __restrict__ be_hh,
    const float* __restrict__ Wenc, const float* __restrict__ benc,
    float* __restrict__ out, int B)
{
    __shared__ SW s;
    __shared__ float4 c_sh[16 * TB];   // 16KB cell state [unit][tid]
    __shared__ float2 h_sh[32 * TB];   // 16KB h double-buffer; lut overlay at end
    const int tid = threadIdx.x;
    const int lane = tid & 31;
    const int warp = tid >> 5;

    // ---- weight fill: real pairs, i/f/o rows pre-scaled by 0.5 --------------
    for (int i = tid; i < 128; i += TB) {
        int r = i >> 1, j = i & 1;
        float sc = ((r >> 4) == 2) ? 1.f : 0.5f;
        s.Wim[i] = pk(W_ih[r * 4 + 2 * j] * sc, W_ih[r * 4 + 2 * j + 1] * sc);
        s.Wie[i] = pk(We_ih[r * 4 + 2 * j] * sc, We_ih[r * 4 + 2 * j + 1] * sc);
    }
    for (int i = tid; i < 512; i += TB) {
        int r = i >> 3, m = i & 7;
        float sc = ((r >> 4) == 2) ? 1.f : 0.5f;
        s.Whm[i] = pk(W_hh[r * 16 + 2 * m] * sc, W_hh[r * 16 + 2 * m + 1] * sc);
        s.Whe[i] = pk(We_hh[r * 16 + 2 * m] * sc, We_hh[r * 16 + 2 * m + 1] * sc);
    }
    for (int i = tid; i < 64; i += TB) {
        float sc = ((i >> 4) == 2) ? 1.f : 0.5f;
        s.Bm[i] = pk((b_ih[i] + b_hh[i]) * sc, 0.f);
        s.Be[i] = pk((be_ih[i] + be_hh[i]) * sc, 0.f);
        s.Wenc[i] = Wenc[i];
    }
    for (int i = tid; i < 156; i += TB) s.Wlf[(i / 13) * 16 + (i % 13)] = Wl[i];
    for (int i = tid; i < 128; i += TB) s.W1[i] = mW1[i];
    if (tid < 32) s.W2[tid] = mW2[tid];
    if (tid < 12) s.Blf[tid] = bl[tid];
    if (tid < 8)  s.B1[tid] = mb1[tid];
    if (tid < 4)  { s.B2m[tid] = mb2[tid]; s.Benc[tid] = benc[tid]; }
    if (tid < 3)  { s.gg[tid] = Wg[tid]; s.gg[4 + tid] = Wg2[tid]; }
    if (tid == 3) { s.gg[3] = bg[0]; s.gg[7] = bg2[0]; }
    __syncthreads();

    const int warpBase = blockIdx.x * ELPB + warp * 128;
    const int e0 = warpBase + lane * EPT;
    const int e0c = (e0 + EPT <= B) ? e0 : (B > EPT ? B - EPT : 0);

    float4* cs = c_sh + tid;
    float* hw = (float*)h_sh;
    u64 hp[4][8];   // h pairs per element
    u64 xe[4][2];
#pragma unroll
    for (int e = 0; e < 4; e++)
#pragma unroll
        for (int m = 0; m < 8; m++) hp[e][m] = 0ull;
#pragma unroll
    for (int k = 0; k < 16; k++) cs[k * TB] = make_float4(0.f, 0.f, 0.f, 0.f);

    // ---------------- phase 1: main LSTM over z_t (coalesced) ----------------
    {
        float4 zv[4], zn[4];
#pragma unroll
        for (int q = 0; q < 4; q++) zv[q] = *(const float4*)(g_zt + (size_t)q * B + e0c);
#pragma unroll 1
        for (int t = 0; t < 12; t++) {
            if (t < 11) {
#pragma unroll
                for (int q = 0; q < 4; q++)
                    zn[q] = *(const float4*)(g_zt + (size_t)((t + 1) * 4 + q) * B + e0c);
            }
#pragma unroll
            for (int e = 0; e < 4; e++) {
                xe[e][0] = pk(COMP(zv[0], e), COMP(zv[1], e));
                xe[e][1] = pk(COMP(zv[2], e), COMP(zv[3], e));
            }
            cell4u(s.Wim, s.Whm, s.Bm, xe, hp, cs, hw, tid);
#pragma unroll
            for (int q = 0; q < 4; q++) zv[q] = zn[q];
        }
    }

    // ------------- epilogue: per-element mlp -> gcn2 -> v_out -> en ----------
#pragma unroll 1
    for (int j = 0; j < EPT; j++) {
        float hs[16];
#pragma unroll
        for (int k = 0; k < 16; k++) {
            float a, b; upk(hp[j][k >> 1], a, b); hs[k] = (k & 1) ? b : a;
        }
        float m1[8];
#pragma unroll
        for (int jj = 0; jj < 8; jj++) {
            float a = s.B1[jj];
#pragma unroll
            for (int k = 0; k < 16; k++) a += hs[k] * s.W1[jj * 16 + k];
            m1[jj] = fmaxf(a, 0.f);
        }
        float mo[4];
#pragma unroll
        for (int n = 0; n < 4; n++) {
            float a = s.B2m[n];
#pragma unroll
            for (int jj = 0; jj < 8; jj++) a += m1[jj] * s.W2[n * 8 + jj];
            mo[n] = a;
        }
        float q0 = s.gg[4], q1 = s.gg[5], q2 = s.gg[6], qb = s.gg[7];
        float x1_0 = mo[1], x1_1 = mo[0] + mo[2], x1_2 = mo[1] + mo[3], x1_3 = mo[2];
        float x2_0 = x1_1, x2_1 = x1_0 + x1_2, x2_2 = x1_1 + x1_3, x2_3 = x1_2;
        float mg[4];
        mg[0] = q0 * mo[0] + q1 * x1_0 + q2 * x2_0 + qb;
        mg[1] = q0 * mo[1] + q1 * x1_1 + q2 * x2_1 + qb;
        mg[2] = q0 * mo[2] + q1 * x1_2 + q2 * x2_2 + qb;
        mg[3] = q0 * mo[3] + q1 * x1_3 + q2 * x2_3 + qb;

        const int e = e0c + j;
        float xr[48];
        {
            const float4* xb = (const float4*)(x + (size_t)e * 48);
#pragma unroll
            for (int q = 0; q < 12; q++) {
                float4 v = xb[q];
                xr[q * 4 + 0] = v.x; xr[q * 4 + 1] = v.y;
                xr[q * 4 + 2] = v.z; xr[q * 4 + 3] = v.w;
            }
        }
        const float g0_ = s.gg[0], g1_ = s.gg[1], g2_ = s.gg[2], gb_ = s.gg[3];
        const bool wr = (e0 + j) < B;
#pragma unroll 1
        for (int t = 0; t < 12; t++) {
            float vc[4];
#pragma unroll
            for (int n = 0; n < 4; n++) {
                float a = s.Blf[t] + mg[n] * s.Wlf[t * 16 + 12];
#pragma unroll
                for (int k = 0; k < 12; k++) a += xr[n * 12 + k] * s.Wlf[t * 16 + k];
                vc[n] = a;
            }
            float xc0 = xr[t], xc1 = xr[12 + t], xc2 = xr[24 + t], xc3 = xr[36 + t];
            float a1_0 = xc1, a1_1 = xc0 + xc2, a1_2 = xc1 + xc3, a1_3 = xc2;
            float a2_0 = a1_1, a2_1 = a1_0 + a1_2, a2_2 = a1_1 + a1_3, a2_3 = a1_2;
            float d1_0 = vc[1], d1_1 = vc[0] + vc[2], d1_2 = vc[1] + vc[3], d1_3 = vc[2];
            float d2_0 = d1_1, d2_1 = d1_0 + d1_2, d2_2 = d1_1 + d1_3, d2_3 = d1_2;
            float en0 = g0_ * xc0 + g1_ * a1_0 + g2_ * a2_0 + gb_ + q0 * vc[0] + q1 * d1_0 + q2 * d2_0 + qb;
            float en1 = g0_ * xc1 + g1_ * a1_1 + g2_ * a2_1 + gb_ + q0 * vc[1] + q1 * d1_1 + q2 * d2_1 + qb;
            float en2 = g0_ * xc2 + g1_ * a1_2 + g2_ * a2_2 + gb_ + q0 * vc[2] + q1 * d1_2 + q2 * d2_2 + qb;
            float en3 = g0_ * xc3 + g1_ * a1_3 + g2_ * a2_3 + gb_ + q0 * vc[3] + q1 * d1_3 + q2 * d2_3 + qb;
            if (wr) {
                g_en[(size_t)(0 * 12 + t) * B + e] = en0;
                g_en[(size_t)(1 * 12 + t) * B + e] = en1;
                g_en[(size_t)(2 * 12 + t) * B + e] = en2;
                g_en[(size_t)(3 * 12 + t) * B + e] = en3;
            }
        }
    }

    // ---------------- phase 3: encoder LSTM over en (coalesced) ---------------
#pragma unroll
    for (int e = 0; e < 4; e++)
#pragma unroll
        for (int m = 0; m < 8; m++) hp[e][m] = 0ull;
#pragma unroll
    for (int k = 0; k < 16; k++) cs[k * TB] = make_float4(0.f, 0.f, 0.f, 0.f);
    {
        float4 ev[4], en2[4];
#pragma unroll
        for (int n = 0; n < 4; n++) ev[n] = *(const float4*)(g_en + (size_t)(n * 12) * B + e0c);
#pragma unroll 1
        for (int t = 0; t < 12; t++) {
            if (t < 11) {
#pragma unroll
                for (int n = 0; n < 4; n++)
                    en2[n] = *(const float4*)(g_en + (size_t)(n * 12 + t + 1) * B + e0c);
            }
#pragma unroll
            for (int e = 0; e < 4; e++) {
                xe[e][0] = pk(COMP(ev[0], e), COMP(ev[1], e));
                xe[e][1] = pk(COMP(ev[2], e), COMP(ev[3], e));
            }
            cell4u(s.Wie, s.Whe, s.Be, xe, hp, cs, hw, tid);
#pragma unroll
            for (int n = 0; n < 4; n++) ev[n] = en2[n];
        }
    }

    // ---------------- final projection -> lut (overlaid on h_sh) -------------
    __syncthreads();   // all warps done with h_sh before lut overlay
    float* lutF = (float*)h_sh;
#pragma unroll 1
    for (int j = 0; j < EPT; j++) {
        float hs[16];
#pragma unroll
        for (int k = 0; k < 16; k++) {
            float a, b; upk(hp[j][k >> 1], a, b); hs[k] = (k & 1) ? b : a;
        }
#pragma unroll
        for (int n = 0; n < 4; n++) {
            float a = s.Benc[n];
#pragma unroll
            for (int k = 0; k < 16; k++) a += hs[k] * s.Wenc[n * 16 + k];
            lutF[(tid * EPT + j) * 4 + n] = a;
        }
    }
    __syncthreads();

    // per-warp block = 128 rows x 48 floats, coalesced
    float4* ob = (float4*)(out + (size_t)warpBase * 48);
#pragma unroll 1
    for (int r = 0; r < 48; r++) {
        int f = r * 32 + lane;
        int el = f / 12;
        int jj = f % 12;
        if (warpBase + el < B) {
            float v = lutF[(warp * 128 + el) * 4 + jj / 3];
            ob[f] = make_float4(v, v, v, v);
        }
    }
}

extern "C" void kernel_launch(void* const* d_in, const int* in_sizes, int n_in,
                              void* d_out, int out_size)
{
    const float* x     = (const float*)d_in[0];
    const float* z     = (const float*)d_in[1];
    const float* W_ih  = (const float*)d_in[2];
    const float* W_hh  = (const float*)d_in[3];
    const float* b_ih  = (const float*)d_in[4];
    const float* b_hh  = (const float*)d_in[5];
    const float* mW1   = (const float*)d_in[6];
    const float* mb1   = (const float*)d_in[7];
    const float* mW2   = (const float*)d_in[8];
    const float* mb2   = (const float*)d_in[9];
    const float* Wg    = (const float*)d_in[10];
    const float* bg    = (const float*)d_in[11];
    const float* Wg2   = (const float*)d_in[12];
    const float* bg2   = (const float*)d_in[13];
    const float* Wl    = (const float*)d_in[14];
    const float* bl    = (const float*)d_in[15];
    const float* We_ih = (const float*)d_in[16];
    const float* We_hh = (const float*)d_in[17];
    const float* be_ih = (const float*)d_in[18];
    const float* be_hh = (const float*)d_in[19];
    const float* Wenc  = (const float*)d_in[20];
    const float* benc  = (const float*)d_in[21];

    int B = in_sizes[0] / 48;   // x is [B, 12, 4]
    zt_kernel<<<(B + 63) / 64, 256>>>(z, B);
    stae_main<<<(B + ELPB - 1) / ELPB, TB>>>(
        x, W_ih, W_hh, b_ih, b_hh, mW1, mb1, mW2, mb2,
        Wg, bg, Wg2, bg2, Wl, bl, We_ih, We_hh, be_ih, be_hh,
        Wenc, benc, (float*)d_out, B);
}